// round 15
// baseline (speedup 1.0000x reference)
#include <cuda_runtime.h>
#include <cstddef>

// x: (8, 16, 3, 256, 256) fp32; out: (128, 2, 256, 256) fp32
// out[bl, ch, hw] = plane(bl*3) - plane((bl-1)*3), zero when bl%16==0; ch0==ch1.
//
// FINAL: fully coalesced, 1 float4/thread, __ldg loads + __stcs streaming
// stores, 512-thread blocks, exact grid. Swept and settled over 14 rounds:
//   cache policy: default / stwt / stcs / evict_last  -> stcs best (-1.8us)
//   vector width: 128b / 256b                         -> 128b best wall
//   ILP: 1 / 2 / 4 / 16-chain                         -> flat
//   block: 256 / 512 / 1024                           -> 512 best (-0.3us)
// Plateau: 15.0 +/- 0.2 us wall = ~6.7 TB/s effective mixed-R/W HBM
// throughput for the 100 MB compulsory traffic. At the roofline.

static constexpr int HW4 = 16384;         // 256*256/4
static constexpr int BL  = 128;           // 8*16
static constexpr int TOTAL4 = BL * HW4;   // 2,097,152 float4 threads (= 4096*512)

__global__ __launch_bounds__(512) void dummyflow_diff_kernel(
    const float4* __restrict__ x, float4* __restrict__ out)
{
    int idx = blockIdx.x * blockDim.x + threadIdx.x;   // grid exact: no guard

    int bl = idx >> 14;         // idx / HW4
    int hw = idx & (HW4 - 1);   // idx % HW4
    int l  = bl & 15;           // warp-uniform: no divergence

    float4 v;
    if (l == 0) {
        v = make_float4(0.f, 0.f, 0.f, 0.f);
    } else {
        size_t cur  = (size_t)(bl * 3)       * HW4 + hw;
        size_t prev = (size_t)((bl - 1) * 3) * HW4 + hw;
        float4 a = __ldg(&x[cur]);
        float4 p = __ldg(&x[prev]);
        v = make_float4(a.x - p.x, a.y - p.y, a.z - p.z, a.w - p.w);
    }

    size_t o = (size_t)(bl * 2) * HW4 + hw;
    __stcs(&out[o], v);         // channel 0 — streaming (evict-first)
    __stcs(&out[o + HW4], v);   // channel 1
}

extern "C" void kernel_launch(void* const* d_in, const int* in_sizes, int n_in,
                              void* d_out, int out_size)
{
    const float4* x = (const float4*)d_in[0];
    float4* out = (float4*)d_out;

    dummyflow_diff_kernel<<<TOTAL4 / 512, 512>>>(x, out);   // 4096 blocks, exact
}

// round 16
// speedup vs baseline: 1.0593x; 1.0593x over previous
#include <cuda_runtime.h>
#include <cstddef>

// x: (8, 16, 3, 256, 256) fp32; out: (128, 2, 256, 256) fp32
// out[bl, ch, hw] = plane(bl*3) - plane((bl-1)*3), zero when bl%16==0; ch0==ch1.
//
// FINAL OPTIMUM (stable across 4 re-measurements; wall 14.8-16.0 us = run
// noise, ncu 15.0-15.7 us): fully coalesced, 1 float4/thread, __ldg loads +
// __stcs streaming stores, 512-thread blocks, exact grid.
// Swept over 15 rounds:
//   cache policy: default / stwt / stcs / evict_last  -> stcs best (-1.8us)
//   vector width: 128b / 256b                         -> 128b best
//   ILP: 1 / 2 / 4 / 16-chain                         -> flat
//   block: 256 / 512 / 1024                           -> 512 best
//   traffic shape: two-read vs chain one-read         -> flat (L2 absorbs)
// At the ~6.7 TB/s effective mixed-R/W HBM roofline for 100 MB compulsory
// traffic (33.5 MB reads + 67 MB writes). No headroom remains.

static constexpr int HW4 = 16384;         // 256*256/4
static constexpr int BL  = 128;           // 8*16
static constexpr int TOTAL4 = BL * HW4;   // 2,097,152 float4 threads (= 4096*512)

__global__ __launch_bounds__(512) void dummyflow_diff_kernel(
    const float4* __restrict__ x, float4* __restrict__ out)
{
    int idx = blockIdx.x * blockDim.x + threadIdx.x;   // grid exact: no guard

    int bl = idx >> 14;         // idx / HW4
    int hw = idx & (HW4 - 1);   // idx % HW4
    int l  = bl & 15;           // warp-uniform: no divergence

    float4 v;
    if (l == 0) {
        v = make_float4(0.f, 0.f, 0.f, 0.f);
    } else {
        size_t cur  = (size_t)(bl * 3)       * HW4 + hw;
        size_t prev = (size_t)((bl - 1) * 3) * HW4 + hw;
        float4 a = __ldg(&x[cur]);
        float4 p = __ldg(&x[prev]);
        v = make_float4(a.x - p.x, a.y - p.y, a.z - p.z, a.w - p.w);
    }

    size_t o = (size_t)(bl * 2) * HW4 + hw;
    __stcs(&out[o], v);         // channel 0 — streaming (evict-first)
    __stcs(&out[o + HW4], v);   // channel 1
}

extern "C" void kernel_launch(void* const* d_in, const int* in_sizes, int n_in,
                              void* d_out, int out_size)
{
    const float4* x = (const float4*)d_in[0];
    float4* out = (float4*)d_out;

    dummyflow_diff_kernel<<<TOTAL4 / 512, 512>>>(x, out);   // 4096 blocks, exact
}